// round 9
// baseline (speedup 1.0000x reference)
#include <cuda_runtime.h>
#include <cstdint>

#define N 4096
#define D 256
#define C 1000
#define BM 128
#define NT (N / BM)                 // 32
#define NTILES (NT * (NT + 1) / 2)  // 528
#define BK 16
#define STAGES 4
#define PITCH 20                    // floats per smem tile row (16 slots + 4 pad)
#define TILE_F (BM * PITCH)         // 2560 floats per operand tile

// Shared memory layout (floats): 4 stages x 4 tiles {A_P,B_P,A_T,B_T}
#define OFF_TILES 0
#define OFF_SQ    (STAGES * 4 * TILE_F)       // 40960
#define OFF_SRED  (OFF_SQ + 512)
#define SMEM_FLOATS (OFF_SRED + 16)
#define SMEM_BYTES (SMEM_FLOATS * 4)          // 165,952 B

__device__ double g_acc[4];
__device__ float  g_sqn[6][N];
// tf32-truncated, k-permuted copies of the 6 feature matrices (24 MB).
__device__ float  g_tf[6][N * D];

// ---------------------------------------------------------------------------
__device__ __forceinline__ uint32_t smem_u32(const void* p) {
    uint32_t a;
    asm("{ .reg .u64 t; cvta.to.shared.u64 t, %1; cvt.u32.u64 %0, t; }" : "=r"(a) : "l"(p));
    return a;
}
__device__ __forceinline__ uint32_t to_tf32(float f) {
    uint32_t u;
    asm("cvt.rna.tf32.f32 %0, %1;" : "=r"(u) : "f"(f));
    return u;
}
__device__ __forceinline__ void mma_tf32(float* d, uint32_t a0, uint32_t a1,
                                         uint32_t a2, uint32_t a3,
                                         uint32_t b0, uint32_t b1) {
    asm volatile(
        "mma.sync.aligned.m16n8k8.row.col.f32.tf32.tf32.f32 "
        "{%0,%1,%2,%3}, {%4,%5,%6,%7}, {%8,%9}, {%0,%1,%2,%3};"
        : "+f"(d[0]), "+f"(d[1]), "+f"(d[2]), "+f"(d[3])
        : "r"(a0), "r"(a1), "r"(a2), "r"(a3), "r"(b0), "r"(b1));
}
#define CP_ASYNC16(dst, src) \
    asm volatile("cp.async.cg.shared.global [%0], [%1], 16;" :: "r"(dst), "l"(src) : "memory")
#define CP_COMMIT() asm volatile("cp.async.commit_group;" ::: "memory")
#define CP_WAIT2()  asm volatile("cp.async.wait_group 2;" ::: "memory")

// ---------------------------------------------------------------------------
__global__ void zero_kernel() {
    if (threadIdx.x < 4) g_acc[threadIdx.x] = 0.0;
}

// Truncate to tf32 and permute k within each 8-group to MMA fragment order:
//   out = {k0,k4,k1,k5,k2,k6,k3,k7}
__global__ void prep_kernel(const float* __restrict__ f0, const float* __restrict__ f1,
                            const float* __restrict__ f2, const float* __restrict__ f3,
                            const float* __restrict__ f4, const float* __restrict__ f5) {
    int idx = blockIdx.x * blockDim.x + threadIdx.x;
    if (idx >= 6 * N * D / 8) return;
    int m   = idx >> 17;
    int rem = idx & 131071;
    const float* src;
    switch (m) {
        case 0: src = f0; break; case 1: src = f1; break; case 2: src = f2; break;
        case 3: src = f3; break; case 4: src = f4; break; default: src = f5; break;
    }
    float4 lo = ((const float4*)src)[rem * 2];
    float4 hi = ((const float4*)src)[rem * 2 + 1];
    uint4 o0, o1;
    o0.x = to_tf32(lo.x); o0.y = to_tf32(hi.x); o0.z = to_tf32(lo.y); o0.w = to_tf32(hi.y);
    o1.x = to_tf32(lo.z); o1.y = to_tf32(hi.z); o1.z = to_tf32(lo.w); o1.w = to_tf32(hi.w);
    ((uint4*)g_tf[m])[rem * 2]     = o0;
    ((uint4*)g_tf[m])[rem * 2 + 1] = o1;
}

// Row squared norms (fp32, full precision), one warp per row.
__global__ void sqn_kernel(const float* __restrict__ f0, const float* __restrict__ f1,
                           const float* __restrict__ f2, const float* __restrict__ f3,
                           const float* __restrict__ f4, const float* __restrict__ f5) {
    int gw   = (blockIdx.x * blockDim.x + threadIdx.x) >> 5;
    int lane = threadIdx.x & 31;
    if (gw >= 6 * N) return;
    int f = gw >> 12;
    int row = gw & (N - 1);
    const float* src;
    switch (f) {
        case 0: src = f0; break; case 1: src = f1; break; case 2: src = f2; break;
        case 3: src = f3; break; case 4: src = f4; break; default: src = f5; break;
    }
    const float4* p = (const float4*)(src + (size_t)row * D);
    float s = 0.f;
#pragma unroll
    for (int i = 0; i < 2; i++) {
        float4 v = p[lane + 32 * i];
        s += v.x * v.x + v.y * v.y + v.z * v.z + v.w * v.w;
    }
#pragma unroll
    for (int o = 16; o; o >>= 1) s += __shfl_xor_sync(0xffffffffu, s, o);
    if (lane == 0) g_sqn[f][row] = s;
}

__global__ void label_kernel(const float* __restrict__ pred,
                             const float* __restrict__ target) {
    __shared__ float sred[256];
    const int n4 = N * C / 4;
    float s = 0.f;
    for (int i = blockIdx.x * blockDim.x + threadIdx.x; i < n4;
         i += gridDim.x * blockDim.x) {
        float4 a = ((const float4*)pred)[i];
        float4 b = ((const float4*)target)[i];
        float dx = a.x - b.x, dy = a.y - b.y, dz = a.z - b.z, dw = a.w - b.w;
        s += dx * dx + dy * dy + dz * dz + dw * dw;
    }
    sred[threadIdx.x] = s;
    __syncthreads();
    for (int o = 128; o; o >>= 1) {
        if (threadIdx.x < o) sred[threadIdx.x] += sred[threadIdx.x + o];
        __syncthreads();
    }
    if (threadIdx.x == 0) atomicAdd(&g_acc[0], (double)sred[0]);
}

// ---------------------------------------------------------------------------
// Tensor-core fused pairwise tile kernel. 512 threads, 16 warps (4x4 grid),
// warp tile 32x32 with BOTH Gram accumulators live (P and T in one k pass).
// 4-stage cp.async pipeline over 4 operand tiles per chunk.
__global__ void __launch_bounds__(512, 1)
pair_kernel() {
    extern __shared__ float sm[];
    const uint32_t sb_tiles = smem_u32(sm + OFF_TILES);

    const int f = blockIdx.y;
    int bi = 0, rem = blockIdx.x;
    while (rem >= NT - bi) { rem -= NT - bi; bi++; }
    const int bj = bi + rem;

    const int tid  = threadIdx.x;
    const int wid  = tid >> 5, lane = tid & 31;
    const int wi   = wid & 3;        // row warp group (32 rows)
    const int wj   = wid >> 2;       // col warp group (32 cols)
    const int tg   = lane >> 2;
    const int q    = lane & 3;
    const int rowI = bi * BM, rowJ = bj * BM;

    if (tid < 128) {
        sm[OFF_SQ +       tid] = g_sqn[f][rowI + tid];
        sm[OFF_SQ + 128 + tid] = g_sqn[f][rowJ + tid];
        sm[OFF_SQ + 256 + tid] = g_sqn[3 + f][rowI + tid];
        sm[OFF_SQ + 384 + tid] = g_sqn[3 + f][rowJ + tid];
    }

    // Copy slots: 512 threads cover 128 rows x 4 16B-segments of each tile.
    const int rA = tid >> 2;
    const int qf = tid & 3;
    const uint32_t dOff = (uint32_t)(rA * PITCH + qf * 4) * 4;

    const float* Pg = g_tf[f];
    const float* Tg = g_tf[3 + f];
    const float* gPA = Pg + (size_t)(rowI + rA) * D + qf * 4;
    const float* gPB = Pg + (size_t)(rowJ + rA) * D + qf * 4;
    const float* gTA = Tg + (size_t)(rowI + rA) * D + qf * 4;
    const float* gTB = Tg + (size_t)(rowJ + rA) * D + qf * 4;

    float accP[2][4][4], accT[2][4][4];
#pragma unroll
    for (int mt = 0; mt < 2; mt++)
#pragma unroll
        for (int nt = 0; nt < 4; nt++)
#pragma unroll
            for (int e = 0; e < 4; e++) { accP[mt][nt][e] = 0.f; accT[mt][nt][e] = 0.f; }

    // Prologue: issue chunks 0..2.
#pragma unroll
    for (int p = 0; p < STAGES - 1; p++) {
        const uint32_t st = sb_tiles + (uint32_t)p * (4 * TILE_F * 4);
        CP_ASYNC16(st + dOff,                   gPA + p * BK);
        CP_ASYNC16(st + TILE_F * 4     + dOff,  gPB + p * BK);
        CP_ASYNC16(st + TILE_F * 8     + dOff,  gTA + p * BK);
        CP_ASYNC16(st + TILE_F * 12    + dOff,  gTB + p * BK);
        CP_COMMIT();
    }

#pragma unroll 1
    for (int c = 0; c < D / BK; c++) {
        CP_WAIT2();                 // chunk c landed
        __syncthreads();

        const float* sPA = sm + OFF_TILES + (c & 3) * 4 * TILE_F;
        const float* sPB = sPA + TILE_F;
        const float* sTA = sPB + TILE_F;
        const float* sTB = sTA + TILE_F;
#pragma unroll
        for (int g = 0; g < 2; g++) {
            uint32_t aP0[2], aP1[2], aP2[2], aP3[2];
            uint32_t aT0[2], aT1[2], aT2[2], aT3[2];
#pragma unroll
            for (int mt = 0; mt < 2; mt++) {
                int rlo = (wi * 32 + mt * 16 + tg) * PITCH + g * 8 + 2 * q;
                int rhi = rlo + 8 * PITCH;
                float2 lo = *(const float2*)&sPA[rlo];
                float2 hi = *(const float2*)&sPA[rhi];
                aP0[mt] = __float_as_uint(lo.x); aP2[mt] = __float_as_uint(lo.y);
                aP1[mt] = __float_as_uint(hi.x); aP3[mt] = __float_as_uint(hi.y);
                lo = *(const float2*)&sTA[rlo];
                hi = *(const float2*)&sTA[rhi];
                aT0[mt] = __float_as_uint(lo.x); aT2[mt] = __float_as_uint(lo.y);
                aT1[mt] = __float_as_uint(hi.x); aT3[mt] = __float_as_uint(hi.y);
            }
#pragma unroll
            for (int nt = 0; nt < 4; nt++) {
                int cb = (wj * 32 + nt * 8 + tg) * PITCH + g * 8 + 2 * q;
                float2 fb = *(const float2*)&sPB[cb];
                uint32_t b0 = __float_as_uint(fb.x), b1 = __float_as_uint(fb.y);
                mma_tf32(accP[0][nt], aP0[0], aP1[0], aP2[0], aP3[0], b0, b1);
                mma_tf32(accP[1][nt], aP0[1], aP1[1], aP2[1], aP3[1], b0, b1);
                fb = *(const float2*)&sTB[cb];
                b0 = __float_as_uint(fb.x); b1 = __float_as_uint(fb.y);
                mma_tf32(accT[0][nt], aT0[0], aT1[0], aT2[0], aT3[0], b0, b1);
                mma_tf32(accT[1][nt], aT0[1], aT1[1], aT2[1], aT3[1], b0, b1);
            }
        }

        // Issue chunk c+3 into buffer (c+3)&3 (its last reader was chunk c-1,
        // protected by this iteration's __syncthreads).
        if (c + STAGES - 1 < D / BK) {
            const int x = c + STAGES - 1;
            const uint32_t st = sb_tiles + (uint32_t)(x & 3) * (4 * TILE_F * 4);
            CP_ASYNC16(st + dOff,                 gPA + x * BK);
            CP_ASYNC16(st + TILE_F * 4   + dOff,  gPB + x * BK);
            CP_ASYNC16(st + TILE_F * 8   + dOff,  gTA + x * BK);
            CP_ASYNC16(st + TILE_F * 12  + dOff,  gTB + x * BK);
            CP_COMMIT();
        }
    }

    // Epilogue: distances for P and T, accumulate (dP - dT)^2.
    const float* sqPi = sm + OFF_SQ;
    const float* sqPj = sqPi + 128;
    const float* sqTi = sqPi + 256;
    const float* sqTj = sqPi + 384;
    float s_total = 0.f;
#pragma unroll
    for (int mt = 0; mt < 2; mt++)
#pragma unroll
        for (int nt = 0; nt < 4; nt++)
#pragma unroll
            for (int e = 0; e < 4; e++) {
                int lr = wi * 32 + mt * 16 + tg + ((e >> 1) << 3);
                int lc = wj * 32 + nt * 8 + 2 * q + (e & 1);
                float sp = sqPi[lr] + sqPj[lc] - 2.f * accP[mt][nt][e];
                float st = sqTi[lr] + sqTj[lc] - 2.f * accT[mt][nt][e];
                float dp = sp > 0.f ? sp * rsqrtf(sp) : 0.f;
                float dt = st > 0.f ? st * rsqrtf(st) : 0.f;
                float d = dp - dt;
                s_total += d * d;
            }

    s_total *= (bi == bj) ? 1.f : 2.f;
#pragma unroll
    for (int o = 16; o; o >>= 1) s_total += __shfl_xor_sync(0xffffffffu, s_total, o);
    if (lane == 0) sm[OFF_SRED + wid] = s_total;
    __syncthreads();
    if (tid == 0) {
        double tot = 0.0;
#pragma unroll
        for (int w = 0; w < 16; w++) tot += (double)sm[OFF_SRED + w];
        atomicAdd(&g_acc[1 + f], tot);
    }
}

// ---------------------------------------------------------------------------
__global__ void final_kernel(float* __restrict__ out) {
    double label = g_acc[0] / ((double)N * (double)C);
    double feat  = (g_acc[1] + g_acc[2] + g_acc[3]) / ((double)N * (double)N);
    out[0] = (float)((1.0 - 0.8) * label + 0.8 * feat / 3.0);
}

// ---------------------------------------------------------------------------
extern "C" void kernel_launch(void* const* d_in, const int* in_sizes, int n_in,
                              void* d_out, int out_size) {
    const float* pred   = (const float*)d_in[0];
    const float* target = (const float*)d_in[1];
    const float* pf0 = (const float*)d_in[2];
    const float* pf1 = (const float*)d_in[3];
    const float* pf2 = (const float*)d_in[4];
    const float* tf0 = (const float*)d_in[5];
    const float* tf1 = (const float*)d_in[6];
    const float* tf2 = (const float*)d_in[7];
    float* out = (float*)d_out;

    static int configured = 0;
    if (!configured) {
        cudaFuncSetAttribute(pair_kernel,
                             cudaFuncAttributeMaxDynamicSharedMemorySize, SMEM_BYTES);
        configured = 1;
    }

    zero_kernel<<<1, 32>>>();
    prep_kernel<<<(6 * N * D / 8 + 255) / 256, 256>>>(pf0, pf1, pf2, tf0, tf1, tf2);
    sqn_kernel<<<(6 * N) / 8, 256>>>(pf0, pf1, pf2, tf0, tf1, tf2);
    label_kernel<<<512, 256>>>(pred, target);

    dim3 grid(NTILES, 3);
    pair_kernel<<<grid, 512, SMEM_BYTES>>>();

    final_kernel<<<1, 1>>>(out);
}

// round 10
// speedup vs baseline: 1.3844x; 1.3844x over previous
#include <cuda_runtime.h>
#include <cstdint>

#define N 4096
#define D 256
#define C 1000
#define BI 256
#define BJ 128
#define BK 16
#define PITCH 24
#define NTI (N / BI)                // 16 row tile-groups
#define NTJ (N / BJ)                // 32 col tiles
#define NTILES 272                  // sum over bi2 of (32 - 2*bi2)

#define A_TILE_F (BI * PITCH)       // 6144 floats
#define B_TILE_F (BJ * PITCH)       // 3072 floats
#define STAGE_F (A_TILE_F + B_TILE_F)

// Shared memory layout (floats)
#define OFF_DP    0                           // 128*256 = 32768 (parked dP)
#define OFF_TILES 32768                       // 2 stages x (A+B) = 18432
#define OFF_SQ    (OFF_TILES + 2 * STAGE_F)   // 768: sqPi256,sqPj128,sqTi256,sqTj128
#define OFF_SRED  (OFF_SQ + 768)
#define SMEM_FLOATS (OFF_SRED + 8)
#define SMEM_BYTES (SMEM_FLOATS * 4)          // 207,936 B

__device__ double g_acc[4];
__device__ float  g_sqn[6][N];
// tf32-truncated, k-permuted copies of the 6 feature matrices (24 MB).
__device__ float  g_tf[6][N * D];

// ---------------------------------------------------------------------------
__device__ __forceinline__ uint32_t smem_u32(const void* p) {
    uint32_t a;
    asm("{ .reg .u64 t; cvta.to.shared.u64 t, %1; cvt.u32.u64 %0, t; }" : "=r"(a) : "l"(p));
    return a;
}
__device__ __forceinline__ uint32_t to_tf32(float f) {
    uint32_t u;
    asm("cvt.rna.tf32.f32 %0, %1;" : "=r"(u) : "f"(f));
    return u;
}
__device__ __forceinline__ void mma_tf32(float* d, uint32_t a0, uint32_t a1,
                                         uint32_t a2, uint32_t a3,
                                         uint32_t b0, uint32_t b1) {
    asm volatile(
        "mma.sync.aligned.m16n8k8.row.col.f32.tf32.tf32.f32 "
        "{%0,%1,%2,%3}, {%4,%5,%6,%7}, {%8,%9}, {%0,%1,%2,%3};"
        : "+f"(d[0]), "+f"(d[1]), "+f"(d[2]), "+f"(d[3])
        : "r"(a0), "r"(a1), "r"(a2), "r"(a3), "r"(b0), "r"(b1));
}
#define CP_ASYNC16(dst, src) \
    asm volatile("cp.async.cg.shared.global [%0], [%1], 16;" :: "r"(dst), "l"(src) : "memory")
#define CP_COMMIT() asm volatile("cp.async.commit_group;" ::: "memory")
#define CP_WAIT0()  asm volatile("cp.async.wait_group 0;" ::: "memory")

// ---------------------------------------------------------------------------
__global__ void zero_kernel() {
    if (threadIdx.x < 4) g_acc[threadIdx.x] = 0.0;
}

// Truncate to tf32 and permute k within each 8-group to MMA fragment order:
//   out = {k0,k4,k1,k5,k2,k6,k3,k7}
__global__ void prep_kernel(const float* __restrict__ f0, const float* __restrict__ f1,
                            const float* __restrict__ f2, const float* __restrict__ f3,
                            const float* __restrict__ f4, const float* __restrict__ f5) {
    int idx = blockIdx.x * blockDim.x + threadIdx.x;
    if (idx >= 6 * N * D / 8) return;
    int m   = idx >> 17;
    int rem = idx & 131071;
    const float* src;
    switch (m) {
        case 0: src = f0; break; case 1: src = f1; break; case 2: src = f2; break;
        case 3: src = f3; break; case 4: src = f4; break; default: src = f5; break;
    }
    float4 lo = ((const float4*)src)[rem * 2];
    float4 hi = ((const float4*)src)[rem * 2 + 1];
    uint4 o0, o1;
    o0.x = to_tf32(lo.x); o0.y = to_tf32(hi.x); o0.z = to_tf32(lo.y); o0.w = to_tf32(hi.y);
    o1.x = to_tf32(lo.z); o1.y = to_tf32(hi.z); o1.z = to_tf32(lo.w); o1.w = to_tf32(hi.w);
    ((uint4*)g_tf[m])[rem * 2]     = o0;
    ((uint4*)g_tf[m])[rem * 2 + 1] = o1;
}

// Row squared norms (fp32, full precision), one warp per row.
__global__ void sqn_kernel(const float* __restrict__ f0, const float* __restrict__ f1,
                           const float* __restrict__ f2, const float* __restrict__ f3,
                           const float* __restrict__ f4, const float* __restrict__ f5) {
    int gw   = (blockIdx.x * blockDim.x + threadIdx.x) >> 5;
    int lane = threadIdx.x & 31;
    if (gw >= 6 * N) return;
    int f = gw >> 12;
    int row = gw & (N - 1);
    const float* src;
    switch (f) {
        case 0: src = f0; break; case 1: src = f1; break; case 2: src = f2; break;
        case 3: src = f3; break; case 4: src = f4; break; default: src = f5; break;
    }
    const float4* p = (const float4*)(src + (size_t)row * D);
    float s = 0.f;
#pragma unroll
    for (int i = 0; i < 2; i++) {
        float4 v = p[lane + 32 * i];
        s += v.x * v.x + v.y * v.y + v.z * v.z + v.w * v.w;
    }
#pragma unroll
    for (int o = 16; o; o >>= 1) s += __shfl_xor_sync(0xffffffffu, s, o);
    if (lane == 0) g_sqn[f][row] = s;
}

__global__ void label_kernel(const float* __restrict__ pred,
                             const float* __restrict__ target) {
    __shared__ float sred[256];
    const int n4 = N * C / 4;
    float s = 0.f;
    for (int i = blockIdx.x * blockDim.x + threadIdx.x; i < n4;
         i += gridDim.x * blockDim.x) {
        float4 a = ((const float4*)pred)[i];
        float4 b = ((const float4*)target)[i];
        float dx = a.x - b.x, dy = a.y - b.y, dz = a.z - b.z, dw = a.w - b.w;
        s += dx * dx + dy * dy + dz * dz + dw * dw;
    }
    sred[threadIdx.x] = s;
    __syncthreads();
    for (int o = 128; o; o >>= 1) {
        if (threadIdx.x < o) sred[threadIdx.x] += sred[threadIdx.x + o];
        __syncthreads();
    }
    if (threadIdx.x == 0) atomicAdd(&g_acc[0], (double)sred[0]);
}

// ---------------------------------------------------------------------------
// Tensor-core fused pairwise kernel. 256x128 block tile, 8 warps (4x2),
// warp tile 64x64 (8 MAC per smem byte). Phase split: Gram(P) -> dP parked in
// smem (128 KB), then Gram(T) -> weighted (dP-dT)^2. Per-element weight
// w in {0,1,2} handles the diagonal inside asymmetric tiles.
__global__ void __launch_bounds__(256, 1)
pair_kernel() {
    extern __shared__ float sm[];
    const uint32_t sb_tiles = smem_u32(sm + OFF_TILES);

    const int f = blockIdx.y;
    // Decode linear tile index -> (bi2, bj) with bj >= 2*bi2.
    int bi2 = 0, rem = blockIdx.x;
    while (rem >= NTJ - 2 * bi2) { rem -= NTJ - 2 * bi2; bi2++; }
    const int bj = 2 * bi2 + rem;

    const int tid  = threadIdx.x;
    const int wid  = tid >> 5, lane = tid & 31;
    const int wi   = wid & 3;        // row warp group (64 rows each)
    const int wj   = wid >> 2;       // col warp group (64 cols each)
    const int tg   = lane >> 2;
    const int q    = lane & 3;
    const int rowI = bi2 * BI, rowJ = bj * BJ;

    // Stage squared norms: [0:256) sqPi, [256:384) sqPj, [384:640) sqTi, [640:768) sqTj
    sm[OFF_SQ + tid]       = g_sqn[f][rowI + tid];
    sm[OFF_SQ + 384 + tid] = g_sqn[3 + f][rowI + tid];
    if (tid < 128) {
        sm[OFF_SQ + 256 + tid] = g_sqn[f][rowJ + tid];
        sm[OFF_SQ + 640 + tid] = g_sqn[3 + f][rowJ + tid];
    }

    // Staging slots: 256 threads; A covers 256 rows via rA+{0,64,128,192},
    // B covers 128 rows via rA+{0,64}; 16B k-segment qf.
    const int rA = tid >> 2;
    const int qf = tid & 3;
    const uint32_t stsBase = (uint32_t)(rA * PITCH + qf * 4) * 4;

    float s_total = 0.f;

#pragma unroll 1
    for (int phase = 0; phase < 2; ++phase) {
        const float* G  = g_tf[phase ? 3 + f : f];
        const float* gA = G + (size_t)(rowI + rA) * D + qf * 4;
        const float* gB = G + (size_t)(rowJ + rA) * D + qf * 4;

        float acc[4][8][4];
#pragma unroll
        for (int mt = 0; mt < 4; mt++)
#pragma unroll
            for (int nt = 0; nt < 8; nt++)
#pragma unroll
                for (int e = 0; e < 4; e++) acc[mt][nt][e] = 0.f;

        // Prologue: issue chunk 0 into buffer 0.
        {
            const uint32_t sA = sb_tiles;
            const uint32_t sB = sA + A_TILE_F * 4;
#pragma unroll
            for (int u = 0; u < 4; u++)
                CP_ASYNC16(sA + stsBase + u * 64 * PITCH * 4, gA + (size_t)u * 64 * D);
#pragma unroll
            for (int u = 0; u < 2; u++)
                CP_ASYNC16(sB + stsBase + u * 64 * PITCH * 4, gB + (size_t)u * 64 * D);
            CP_COMMIT();
        }

#pragma unroll 1
        for (int c = 0; c < D / BK; c++) {
            CP_WAIT0();              // chunk c landed (this thread's copies)
            __syncthreads();         // everyone's copies visible; buffers safe

            // Prefetch chunk c+1 into the other buffer (overlaps compute).
            if (c + 1 < D / BK) {
                const uint32_t sA = sb_tiles + (uint32_t)((c + 1) & 1) * STAGE_F * 4;
                const uint32_t sB = sA + A_TILE_F * 4;
                const float* pA = gA + (c + 1) * BK;
                const float* pB = gB + (c + 1) * BK;
#pragma unroll
                for (int u = 0; u < 4; u++)
                    CP_ASYNC16(sA + stsBase + u * 64 * PITCH * 4, pA + (size_t)u * 64 * D);
#pragma unroll
                for (int u = 0; u < 2; u++)
                    CP_ASYNC16(sB + stsBase + u * 64 * PITCH * 4, pB + (size_t)u * 64 * D);
                CP_COMMIT();
            }

            const float* sA = sm + OFF_TILES + (c & 1) * STAGE_F;
            const float* sB = sA + A_TILE_F;
#pragma unroll
            for (int g = 0; g < 2; g++) {
                uint32_t a0[4], a1[4], a2[4], a3[4], b0[8], b1[8];
#pragma unroll
                for (int mt = 0; mt < 4; mt++) {
                    int rlo = (wi * 64 + mt * 16 + tg) * PITCH + g * 8 + 2 * q;
                    float2 lo = *(const float2*)&sA[rlo];
                    float2 hi = *(const float2*)&sA[rlo + 8 * PITCH];
                    a0[mt] = __float_as_uint(lo.x); a2[mt] = __float_as_uint(lo.y);
                    a1[mt] = __float_as_uint(hi.x); a3[mt] = __float_as_uint(hi.y);
                }
#pragma unroll
                for (int nt = 0; nt < 8; nt++) {
                    float2 fb = *(const float2*)&sB[(wj * 64 + nt * 8 + tg) * PITCH + g * 8 + 2 * q];
                    b0[nt] = __float_as_uint(fb.x);
                    b1[nt] = __float_as_uint(fb.y);
                }
#pragma unroll
                for (int mt = 0; mt < 4; mt++)
#pragma unroll
                    for (int nt = 0; nt < 8; nt++)
                        mma_tf32(acc[mt][nt], a0[mt], a1[mt], a2[mt], a3[mt],
                                 b0[nt], b1[nt]);
            }
        }

        // Epilogue.
        const float* sqi = sm + OFF_SQ + phase * 384;
        const float* sqj = sqi + 256;
#pragma unroll
        for (int mt = 0; mt < 4; mt++)
#pragma unroll
            for (int nt = 0; nt < 8; nt++)
#pragma unroll
                for (int e = 0; e < 4; e++) {
                    int lr = wi * 64 + mt * 16 + tg + ((e >> 1) << 3);
                    int lc = wj * 64 + nt * 8 + 2 * q + (e & 1);
                    float sq = sqi[lr] + sqj[lc] - 2.f * acc[mt][nt][e];
                    float dd = sq > 0.f ? sq * rsqrtf(sq) : 0.f;
                    int slot = OFF_DP + ((mt * 8 + nt) * 4 + e) * 256 + tid;
                    if (phase == 0) {
                        sm[slot] = dd;
                    } else {
                        int gi = rowI + lr, gj = rowJ + lc;
                        float w = (gj > gi) ? 2.f : (gj == gi ? 1.f : 0.f);
                        float d = sm[slot] - dd;
                        s_total += w * d * d;
                    }
                }
    }

#pragma unroll
    for (int o = 16; o; o >>= 1) s_total += __shfl_xor_sync(0xffffffffu, s_total, o);
    if (lane == 0) sm[OFF_SRED + wid] = s_total;
    __syncthreads();
    if (tid == 0) {
        double tot = 0.0;
#pragma unroll
        for (int w = 0; w < 8; w++) tot += (double)sm[OFF_SRED + w];
        atomicAdd(&g_acc[1 + f], tot);
    }
}

// ---------------------------------------------------------------------------
__global__ void final_kernel(float* __restrict__ out) {
    double label = g_acc[0] / ((double)N * (double)C);
    double feat  = (g_acc[1] + g_acc[2] + g_acc[3]) / ((double)N * (double)N);
    out[0] = (float)((1.0 - 0.8) * label + 0.8 * feat / 3.0);
}

// ---------------------------------------------------------------------------
extern "C" void kernel_launch(void* const* d_in, const int* in_sizes, int n_in,
                              void* d_out, int out_size) {
    const float* pred   = (const float*)d_in[0];
    const float* target = (const float*)d_in[1];
    const float* pf0 = (const float*)d_in[2];
    const float* pf1 = (const float*)d_in[3];
    const float* pf2 = (const float*)d_in[4];
    const float* tf0 = (const float*)d_in[5];
    const float* tf1 = (const float*)d_in[6];
    const float* tf2 = (const float*)d_in[7];
    float* out = (float*)d_out;

    static int configured = 0;
    if (!configured) {
        cudaFuncSetAttribute(pair_kernel,
                             cudaFuncAttributeMaxDynamicSharedMemorySize, SMEM_BYTES);
        configured = 1;
    }

    zero_kernel<<<1, 32>>>();
    prep_kernel<<<(6 * N * D / 8 + 255) / 256, 256>>>(pf0, pf1, pf2, tf0, tf1, tf2);
    sqn_kernel<<<(6 * N) / 8, 256>>>(pf0, pf1, pf2, tf0, tf1, tf2);
    label_kernel<<<512, 256>>>(pred, target);

    dim3 grid(NTILES, 3);
    pair_kernel<<<grid, 256, SMEM_BYTES>>>();

    final_kernel<<<1, 1>>>(out);
}

// round 11
// speedup vs baseline: 2.2181x; 1.6022x over previous
#include <cuda_runtime.h>
#include <cuda_bf16.h>
#include <cstdint>

#define N 4096
#define D 256
#define C 1000
#define BI 256
#define BJ 128
#define NTJ (N / BJ)                // 32 col tiles
#define NTILES 272                  // sum over bi2 of (32 - 2*bi2)
#define NCHUNK 8                    // 8 chunks of 32 k

#define PITCH_U 24                  // u32 per smem tile row (16 data + 8 pad)
#define A_TILE_U (BI * PITCH_U)     // 6144 u32
#define B_TILE_U (BJ * PITCH_U)     // 3072 u32
#define STAGE_U (A_TILE_U + B_TILE_U)

// Shared memory layout (32-bit words)
#define OFF_DP    0                           // 128*256 = 32768 (parked dP, f32)
#define OFF_TILES 32768                       // 2 stages x (A+B) = 18432 u32
#define OFF_SQ    (OFF_TILES + 2 * STAGE_U)   // 768 f32
#define OFF_SRED  (OFF_SQ + 768)
#define SMEM_WORDS (OFF_SRED + 8)
#define SMEM_BYTES (SMEM_WORDS * 4)           // 207,904 B

__device__ double g_acc[4];
__device__ float  g_sqn[6][N];
// bf16, k-pair-permuted copies of the 6 feature matrices (12 MB).
// Each u32 = bf16x2 (even k in low half); pair order per 16-k group: {0,4,1,5,2,6,3,7}.
__device__ uint32_t g_bf[6][N * D / 2];

// ---------------------------------------------------------------------------
__device__ __forceinline__ uint32_t smem_u32(const void* p) {
    uint32_t a;
    asm("{ .reg .u64 t; cvta.to.shared.u64 t, %1; cvt.u32.u64 %0, t; }" : "=r"(a) : "l"(p));
    return a;
}
__device__ __forceinline__ uint32_t pack_bf16(float lo, float hi) {
    __nv_bfloat162 v = __floats2bfloat162_rn(lo, hi);   // .x = lo (low half)
    return *reinterpret_cast<uint32_t*>(&v);
}
__device__ __forceinline__ void mma_bf16(float* d, uint32_t a0, uint32_t a1,
                                         uint32_t a2, uint32_t a3,
                                         uint32_t b0, uint32_t b1) {
    asm volatile(
        "mma.sync.aligned.m16n8k16.row.col.f32.bf16.bf16.f32 "
        "{%0,%1,%2,%3}, {%4,%5,%6,%7}, {%8,%9}, {%0,%1,%2,%3};"
        : "+f"(d[0]), "+f"(d[1]), "+f"(d[2]), "+f"(d[3])
        : "r"(a0), "r"(a1), "r"(a2), "r"(a3), "r"(b0), "r"(b1));
}
#define CP_ASYNC16(dst, src) \
    asm volatile("cp.async.cg.shared.global [%0], [%1], 16;" :: "r"(dst), "l"(src) : "memory")
#define CP_COMMIT() asm volatile("cp.async.commit_group;" ::: "memory")
#define CP_WAIT0()  asm volatile("cp.async.wait_group 0;" ::: "memory")

// ---------------------------------------------------------------------------
__global__ void zero_kernel() {
    if (threadIdx.x < 4) g_acc[threadIdx.x] = 0.0;
}

// Convert fp32 -> bf16 pairs, permuting the 8 k-pairs of each 16-k group to
// fragment order {p0,p4,p1,p5,p2,p6,p3,p7}. One thread per 16-k group.
__global__ void prep_kernel(const float* __restrict__ f0, const float* __restrict__ f1,
                            const float* __restrict__ f2, const float* __restrict__ f3,
                            const float* __restrict__ f4, const float* __restrict__ f5) {
    int idx = blockIdx.x * blockDim.x + threadIdx.x;
    if (idx >= 6 * N * D / 16) return;
    int m   = idx >> 16;             // / 65536
    int rem = idx & 65535;
    const float* src;
    switch (m) {
        case 0: src = f0; break; case 1: src = f1; break; case 2: src = f2; break;
        case 3: src = f3; break; case 4: src = f4; break; default: src = f5; break;
    }
    const float4* p = (const float4*)src + rem * 4;
    float4 v0 = p[0], v1 = p[1], v2 = p[2], v3 = p[3];
    // pairs: p0={v0.x,v0.y} p1={v0.z,v0.w} p2={v1.x,v1.y} p3={v1.z,v1.w}
    //        p4={v2.x,v2.y} p5={v2.z,v2.w} p6={v3.x,v3.y} p7={v3.z,v3.w}
    uint4 o0, o1;
    o0.x = pack_bf16(v0.x, v0.y);   // p0
    o0.y = pack_bf16(v2.x, v2.y);   // p4
    o0.z = pack_bf16(v0.z, v0.w);   // p1
    o0.w = pack_bf16(v2.z, v2.w);   // p5
    o1.x = pack_bf16(v1.x, v1.y);   // p2
    o1.y = pack_bf16(v3.x, v3.y);   // p6
    o1.z = pack_bf16(v1.z, v1.w);   // p3
    o1.w = pack_bf16(v3.z, v3.w);   // p7
    ((uint4*)&g_bf[m][(size_t)rem * 8])[0] = o0;
    ((uint4*)&g_bf[m][(size_t)rem * 8])[1] = o1;
}

// Row squared norms (fp32, full precision), one warp per row.
__global__ void sqn_kernel(const float* __restrict__ f0, const float* __restrict__ f1,
                           const float* __restrict__ f2, const float* __restrict__ f3,
                           const float* __restrict__ f4, const float* __restrict__ f5) {
    int gw   = (blockIdx.x * blockDim.x + threadIdx.x) >> 5;
    int lane = threadIdx.x & 31;
    if (gw >= 6 * N) return;
    int f = gw >> 12;
    int row = gw & (N - 1);
    const float* src;
    switch (f) {
        case 0: src = f0; break; case 1: src = f1; break; case 2: src = f2; break;
        case 3: src = f3; break; case 4: src = f4; break; default: src = f5; break;
    }
    const float4* p = (const float4*)(src + (size_t)row * D);
    float s = 0.f;
#pragma unroll
    for (int i = 0; i < 2; i++) {
        float4 v = p[lane + 32 * i];
        s += v.x * v.x + v.y * v.y + v.z * v.z + v.w * v.w;
    }
#pragma unroll
    for (int o = 16; o; o >>= 1) s += __shfl_xor_sync(0xffffffffu, s, o);
    if (lane == 0) g_sqn[f][row] = s;
}

__global__ void label_kernel(const float* __restrict__ pred,
                             const float* __restrict__ target) {
    __shared__ float sred[256];
    const int n4 = N * C / 4;
    float s = 0.f;
    for (int i = blockIdx.x * blockDim.x + threadIdx.x; i < n4;
         i += gridDim.x * blockDim.x) {
        float4 a = ((const float4*)pred)[i];
        float4 b = ((const float4*)target)[i];
        float dx = a.x - b.x, dy = a.y - b.y, dz = a.z - b.z, dw = a.w - b.w;
        s += dx * dx + dy * dy + dz * dz + dw * dw;
    }
    sred[threadIdx.x] = s;
    __syncthreads();
    for (int o = 128; o; o >>= 1) {
        if (threadIdx.x < o) sred[threadIdx.x] += sred[threadIdx.x + o];
        __syncthreads();
    }
    if (threadIdx.x == 0) atomicAdd(&g_acc[0], (double)sred[0]);
}

// ---------------------------------------------------------------------------
// bf16 tensor-core fused pairwise kernel. 256x128 block tile, 8 warps (4x2),
// warp tile 64x64, m16n8k16. Phase split: Gram(P) -> dP parked in smem, then
// Gram(T) -> weighted (dP-dT)^2. Diagonal weight = 0 (reference diag is 0,
// and this kills the bf16 cancellation hazard at i==j).
__global__ void __launch_bounds__(256, 1)
pair_kernel() {
    extern __shared__ float sm[];
    uint32_t* smu = (uint32_t*)sm;
    const uint32_t sb_tiles = smem_u32(sm + OFF_TILES);

    const int f = blockIdx.y;
    int bi2 = 0, rem = blockIdx.x;
    while (rem >= NTJ - 2 * bi2) { rem -= NTJ - 2 * bi2; bi2++; }
    const int bj = 2 * bi2 + rem;

    const int tid  = threadIdx.x;
    const int wid  = tid >> 5, lane = tid & 31;
    const int wi   = wid & 3;        // row warp group (64 rows)
    const int wj   = wid >> 2;       // col warp group (64 cols)
    const int tg   = lane >> 2;
    const int q    = lane & 3;
    const int rowI = bi2 * BI, rowJ = bj * BJ;

    // Squared norms: [0:256) sqPi, [256:384) sqPj, [384:640) sqTi, [640:768) sqTj
    sm[OFF_SQ + tid]       = g_sqn[f][rowI + tid];
    sm[OFF_SQ + 384 + tid] = g_sqn[3 + f][rowI + tid];
    if (tid < 128) {
        sm[OFF_SQ + 256 + tid] = g_sqn[f][rowJ + tid];
        sm[OFF_SQ + 640 + tid] = g_sqn[3 + f][rowJ + tid];
    }

    // Staging: row rA, 16B segment qf (4 segments cover the 64B chunk row).
    const int rA = tid >> 2;
    const int qf = tid & 3;
    const uint32_t stsBase = (uint32_t)(rA * PITCH_U + qf * 4) * 4;

    float s_total = 0.f;

#pragma unroll 1
    for (int phase = 0; phase < 2; ++phase) {
        const uint32_t* G  = g_bf[phase ? 3 + f : f];
        const uint32_t* gA = G + (size_t)(rowI + rA) * (D / 2) + qf * 4;
        const uint32_t* gB = G + (size_t)(rowJ + rA) * (D / 2) + qf * 4;

        float acc[4][8][4];
#pragma unroll
        for (int mt = 0; mt < 4; mt++)
#pragma unroll
            for (int nt = 0; nt < 8; nt++)
#pragma unroll
                for (int e = 0; e < 4; e++) acc[mt][nt][e] = 0.f;

        // Prologue: chunk 0 -> buffer 0.
        {
            const uint32_t sA = sb_tiles;
            const uint32_t sB = sA + A_TILE_U * 4;
#pragma unroll
            for (int u = 0; u < 4; u++)
                CP_ASYNC16(sA + stsBase + u * 64 * PITCH_U * 4, gA + (size_t)u * 64 * (D / 2));
#pragma unroll
            for (int u = 0; u < 2; u++)
                CP_ASYNC16(sB + stsBase + u * 64 * PITCH_U * 4, gB + (size_t)u * 64 * (D / 2));
            CP_COMMIT();
        }

#pragma unroll 1
        for (int c = 0; c < NCHUNK; c++) {
            CP_WAIT0();
            __syncthreads();

            // Prefetch chunk c+1 into the other buffer.
            if (c + 1 < NCHUNK) {
                const uint32_t sA = sb_tiles + (uint32_t)((c + 1) & 1) * STAGE_U * 4;
                const uint32_t sB = sA + A_TILE_U * 4;
                const uint32_t* pA = gA + (c + 1) * 16;
                const uint32_t* pB = gB + (c + 1) * 16;
#pragma unroll
                for (int u = 0; u < 4; u++)
                    CP_ASYNC16(sA + stsBase + u * 64 * PITCH_U * 4, pA + (size_t)u * 64 * (D / 2));
#pragma unroll
                for (int u = 0; u < 2; u++)
                    CP_ASYNC16(sB + stsBase + u * 64 * PITCH_U * 4, pB + (size_t)u * 64 * (D / 2));
                CP_COMMIT();
            }

            const uint32_t* sA = smu + OFF_TILES + (c & 1) * STAGE_U;
            const uint32_t* sB = sA + A_TILE_U;
#pragma unroll
            for (int g = 0; g < 2; g++) {
                uint32_t a0[4], a1[4], a2[4], a3[4], b0[8], b1[8];
#pragma unroll
                for (int mt = 0; mt < 4; mt++) {
                    int off = (wi * 64 + mt * 16 + tg) * PITCH_U + g * 8 + 2 * q;
                    uint2 lo = *(const uint2*)&sA[off];
                    uint2 hi = *(const uint2*)&sA[off + 8 * PITCH_U];
                    a0[mt] = lo.x; a2[mt] = lo.y;
                    a1[mt] = hi.x; a3[mt] = hi.y;
                }
#pragma unroll
                for (int nt = 0; nt < 8; nt++) {
                    uint2 bb = *(const uint2*)&sB[(wj * 64 + nt * 8 + tg) * PITCH_U + g * 8 + 2 * q];
                    b0[nt] = bb.x; b1[nt] = bb.y;
                }
#pragma unroll
                for (int mt = 0; mt < 4; mt++)
#pragma unroll
                    for (int nt = 0; nt < 8; nt++)
                        mma_bf16(acc[mt][nt], a0[mt], a1[mt], a2[mt], a3[mt],
                                 b0[nt], b1[nt]);
            }
        }

        // Epilogue.
        const float* sqi = sm + OFF_SQ + phase * 384;
        const float* sqj = sqi + 256;
#pragma unroll
        for (int mt = 0; mt < 4; mt++)
#pragma unroll
            for (int nt = 0; nt < 8; nt++)
#pragma unroll
                for (int e = 0; e < 4; e++) {
                    int lr = wi * 64 + mt * 16 + tg + ((e >> 1) << 3);
                    int lc = wj * 64 + nt * 8 + 2 * q + (e & 1);
                    float sq = sqi[lr] + sqj[lc] - 2.f * acc[mt][nt][e];
                    float dd = sq > 0.f ? sq * rsqrtf(sq) : 0.f;
                    int slot = OFF_DP + ((mt * 8 + nt) * 4 + e) * 256 + tid;
                    if (phase == 0) {
                        sm[slot] = dd;
                    } else {
                        int gi = rowI + lr, gj = rowJ + lc;
                        float w = (gj > gi) ? 2.f : 0.f;   // diag contributes 0
                        float d = sm[slot] - dd;
                        s_total += w * d * d;
                    }
                }
    }

#pragma unroll
    for (int o = 16; o; o >>= 1) s_total += __shfl_xor_sync(0xffffffffu, s_total, o);
    if (lane == 0) sm[OFF_SRED + wid] = s_total;
    __syncthreads();
    if (tid == 0) {
        double tot = 0.0;
#pragma unroll
        for (int w = 0; w < 8; w++) tot += (double)sm[OFF_SRED + w];
        atomicAdd(&g_acc[1 + f], tot);
    }
}

// ---------------------------------------------------------------------------
__global__ void final_kernel(float* __restrict__ out) {
    double label = g_acc[0] / ((double)N * (double)C);
    double feat  = (g_acc[1] + g_acc[2] + g_acc[3]) / ((double)N * (double)N);
    out[0] = (float)((1.0 - 0.8) * label + 0.8 * feat / 3.0);
}

// ---------------------------------------------------------------------------
extern "C" void kernel_launch(void* const* d_in, const int* in_sizes, int n_in,
                              void* d_out, int out_size) {
    const float* pred   = (const float*)d_in[0];
    const float* target = (const float*)d_in[1];
    const float* pf0 = (const float*)d_in[2];
    const float* pf1 = (const float*)d_in[3];
    const float* pf2 = (const float*)d_in[4];
    const float* tf0 = (const float*)d_in[5];
    const float* tf1 = (const float*)d_in[6];
    const float* tf2 = (const float*)d_in[7];
    float* out = (float*)d_out;

    static int configured = 0;
    if (!configured) {
        cudaFuncSetAttribute(pair_kernel,
                             cudaFuncAttributeMaxDynamicSharedMemorySize, SMEM_BYTES);
        configured = 1;
    }

    zero_kernel<<<1, 32>>>();
    prep_kernel<<<(6 * N * D / 16 + 255) / 256, 256>>>(pf0, pf1, pf2, tf0, tf1, tf2);
    sqn_kernel<<<(6 * N) / 8, 256>>>(pf0, pf1, pf2, tf0, tf1, tf2);
    label_kernel<<<512, 256>>>(pred, target);

    dim3 grid(NTILES, 3);
    pair_kernel<<<grid, 256, SMEM_BYTES>>>();

    final_kernel<<<1, 1>>>(out);
}

// round 12
// speedup vs baseline: 2.2751x; 1.0257x over previous
#include <cuda_runtime.h>
#include <cuda_bf16.h>
#include <cstdint>

#define N 4096
#define D 256
#define C 1000
#define BI 256
#define BJ 128
#define NTJ (N / BJ)                // 32 col tiles
#define NTILES 272                  // sum over bi2 of (32 - 2*bi2)
#define NCHUNK 8                    // 8 chunks of 32 k

#define PITCH_U 24                  // u32 per smem tile row (16 data + 8 pad)
#define A_TILE_U (BI * PITCH_U)     // 6144 u32
#define B_TILE_U (BJ * PITCH_U)     // 3072 u32
#define STAGE_U (A_TILE_U + B_TILE_U)

// Shared memory layout (32-bit words)
#define OFF_DP    0                           // 128*256 = 32768 (parked dP, f32)
#define OFF_TILES 32768                       // 2 stages x (A+B) = 18432 u32
#define OFF_SQ    (OFF_TILES + 2 * STAGE_U)   // 768 f32
#define OFF_SRED  (OFF_SQ + 768)
#define SMEM_WORDS (OFF_SRED + 8)
#define SMEM_BYTES (SMEM_WORDS * 4)           // 207,904 B

__device__ double g_acc[4];
__device__ float  g_sqn[6][N];
// bf16, k-pair-permuted copies of the 6 feature matrices (12 MB).
// Each u32 = bf16x2 (even k low); pair order per 16-k group: {0,4,1,5,2,6,3,7}.
__device__ uint32_t g_bf[6][N * D / 2];

// ---------------------------------------------------------------------------
__device__ __forceinline__ uint32_t smem_u32(const void* p) {
    uint32_t a;
    asm("{ .reg .u64 t; cvta.to.shared.u64 t, %1; cvt.u32.u64 %0, t; }" : "=r"(a) : "l"(p));
    return a;
}
__device__ __forceinline__ uint32_t pack_bf16(float lo, float hi) {
    __nv_bfloat162 v = __floats2bfloat162_rn(lo, hi);   // .x = lo (low half)
    return *reinterpret_cast<uint32_t*>(&v);
}
__device__ __forceinline__ void mma_bf16(float* d, uint32_t a0, uint32_t a1,
                                         uint32_t a2, uint32_t a3,
                                         uint32_t b0, uint32_t b1) {
    asm volatile(
        "mma.sync.aligned.m16n8k16.row.col.f32.bf16.bf16.f32 "
        "{%0,%1,%2,%3}, {%4,%5,%6,%7}, {%8,%9}, {%0,%1,%2,%3};"
        : "+f"(d[0]), "+f"(d[1]), "+f"(d[2]), "+f"(d[3])
        : "r"(a0), "r"(a1), "r"(a2), "r"(a3), "r"(b0), "r"(b1));
}
#define CP_ASYNC16(dst, src) \
    asm volatile("cp.async.cg.shared.global [%0], [%1], 16;" :: "r"(dst), "l"(src) : "memory")
#define CP_COMMIT() asm volatile("cp.async.commit_group;" ::: "memory")
#define CP_WAIT0()  asm volatile("cp.async.wait_group 0;" ::: "memory")

// ---------------------------------------------------------------------------
// Fused prep: fp32 -> bf16 pair-permuted copy + row squared norms + g_acc zero.
// One thread per 16-k group; 16 consecutive lanes = one row -> segmented
// shfl reduce gives the fp32 row norm with no extra global reads.
__global__ void prep_kernel(const float* __restrict__ f0, const float* __restrict__ f1,
                            const float* __restrict__ f2, const float* __restrict__ f3,
                            const float* __restrict__ f4, const float* __restrict__ f5) {
    int idx = blockIdx.x * blockDim.x + threadIdx.x;
    if (blockIdx.x == 0 && threadIdx.x < 4) g_acc[threadIdx.x] = 0.0;
    if (idx >= 6 * N * D / 16) return;
    int m   = idx >> 16;             // / 65536 groups per matrix
    int rem = idx & 65535;
    const float* src;
    switch (m) {
        case 0: src = f0; break; case 1: src = f1; break; case 2: src = f2; break;
        case 3: src = f3; break; case 4: src = f4; break; default: src = f5; break;
    }
    const float4* p = (const float4*)src + rem * 4;
    float4 v0 = p[0], v1 = p[1], v2 = p[2], v3 = p[3];

    // Row-norm partial (fp32, before truncation).
    float s = v0.x * v0.x + v0.y * v0.y + v0.z * v0.z + v0.w * v0.w
            + v1.x * v1.x + v1.y * v1.y + v1.z * v1.z + v1.w * v1.w
            + v2.x * v2.x + v2.y * v2.y + v2.z * v2.z + v2.w * v2.w
            + v3.x * v3.x + v3.y * v3.y + v3.z * v3.z + v3.w * v3.w;
#pragma unroll
    for (int o = 8; o; o >>= 1) s += __shfl_xor_sync(0xffffffffu, s, o);
    if ((threadIdx.x & 15) == 0) g_sqn[m][rem >> 4] = s;

    // bf16 pair-permuted store: {p0,p4,p1,p5,p2,p6,p3,p7}.
    uint4 o0, o1;
    o0.x = pack_bf16(v0.x, v0.y);   // p0
    o0.y = pack_bf16(v2.x, v2.y);   // p4
    o0.z = pack_bf16(v0.z, v0.w);   // p1
    o0.w = pack_bf16(v2.z, v2.w);   // p5
    o1.x = pack_bf16(v1.x, v1.y);   // p2
    o1.y = pack_bf16(v3.x, v3.y);   // p6
    o1.z = pack_bf16(v1.z, v1.w);   // p3
    o1.w = pack_bf16(v3.z, v3.w);   // p7
    ((uint4*)&g_bf[m][(size_t)rem * 8])[0] = o0;
    ((uint4*)&g_bf[m][(size_t)rem * 8])[1] = o1;
}

__global__ void label_kernel(const float* __restrict__ pred,
                             const float* __restrict__ target) {
    __shared__ float sred[256];
    const int n4 = N * C / 4;
    float s = 0.f;
    for (int i = blockIdx.x * blockDim.x + threadIdx.x; i < n4;
         i += gridDim.x * blockDim.x) {
        float4 a = ((const float4*)pred)[i];
        float4 b = ((const float4*)target)[i];
        float dx = a.x - b.x, dy = a.y - b.y, dz = a.z - b.z, dw = a.w - b.w;
        s += dx * dx + dy * dy + dz * dz + dw * dw;
    }
    sred[threadIdx.x] = s;
    __syncthreads();
    for (int o = 128; o; o >>= 1) {
        if (threadIdx.x < o) sred[threadIdx.x] += sred[threadIdx.x + o];
        __syncthreads();
    }
    if (threadIdx.x == 0) atomicAdd(&g_acc[0], (double)sred[0]);
}

// ---------------------------------------------------------------------------
// bf16 tensor-core fused pairwise kernel. 256x128 block tile, 8 warps (4x2),
// warp tile 64x64, m16n8k16. Phase split: Gram(P) -> dP parked in smem, then
// Gram(T) -> weighted (dP-dT)^2. Diagonal weight = 0 (reference diag is 0,
// which also kills the bf16 cancellation hazard at i==j).
__global__ void __launch_bounds__(256, 1)
pair_kernel() {
    extern __shared__ float sm[];
    uint32_t* smu = (uint32_t*)sm;
    const uint32_t sb_tiles = smem_u32(sm + OFF_TILES);

    const int f = blockIdx.y;
    int bi2 = 0, rem = blockIdx.x;
    while (rem >= NTJ - 2 * bi2) { rem -= NTJ - 2 * bi2; bi2++; }
    const int bj = 2 * bi2 + rem;

    const int tid  = threadIdx.x;
    const int wid  = tid >> 5, lane = tid & 31;
    const int wi   = wid & 3;        // row warp group (64 rows)
    const int wj   = wid >> 2;       // col warp group (64 cols)
    const int tg   = lane >> 2;
    const int q    = lane & 3;
    const int rowI = bi2 * BI, rowJ = bj * BJ;

    // Squared norms: [0:256) sqPi, [256:384) sqPj, [384:640) sqTi, [640:768) sqTj
    sm[OFF_SQ + tid]       = g_sqn[f][rowI + tid];
    sm[OFF_SQ + 384 + tid] = g_sqn[3 + f][rowI + tid];
    if (tid < 128) {
        sm[OFF_SQ + 256 + tid] = g_sqn[f][rowJ + tid];
        sm[OFF_SQ + 640 + tid] = g_sqn[3 + f][rowJ + tid];
    }

    // Staging: row rA, 16B segment qf.
    const int rA = tid >> 2;
    const int qf = tid & 3;
    const uint32_t stsBase = (uint32_t)(rA * PITCH_U + qf * 4) * 4;

    float s_total = 0.f;

#pragma unroll 1
    for (int phase = 0; phase < 2; ++phase) {
        const uint32_t* G  = g_bf[phase ? 3 + f : f];
        const uint32_t* gA = G + (size_t)(rowI + rA) * (D / 2) + qf * 4;
        const uint32_t* gB = G + (size_t)(rowJ + rA) * (D / 2) + qf * 4;

        float acc[4][8][4];
#pragma unroll
        for (int mt = 0; mt < 4; mt++)
#pragma unroll
            for (int nt = 0; nt < 8; nt++)
#pragma unroll
                for (int e = 0; e < 4; e++) acc[mt][nt][e] = 0.f;

        // Prologue: chunk 0 -> buffer 0.
        {
            const uint32_t sA = sb_tiles;
            const uint32_t sB = sA + A_TILE_U * 4;
#pragma unroll
            for (int u = 0; u < 4; u++)
                CP_ASYNC16(sA + stsBase + u * 64 * PITCH_U * 4, gA + (size_t)u * 64 * (D / 2));
#pragma unroll
            for (int u = 0; u < 2; u++)
                CP_ASYNC16(sB + stsBase + u * 64 * PITCH_U * 4, gB + (size_t)u * 64 * (D / 2));
            CP_COMMIT();
        }

#pragma unroll 1
        for (int c = 0; c < NCHUNK; c++) {
            CP_WAIT0();
            __syncthreads();

            // Prefetch chunk c+1 into the other buffer.
            if (c + 1 < NCHUNK) {
                const uint32_t sA = sb_tiles + (uint32_t)((c + 1) & 1) * STAGE_U * 4;
                const uint32_t sB = sA + A_TILE_U * 4;
                const uint32_t* pA = gA + (c + 1) * 16;
                const uint32_t* pB = gB + (c + 1) * 16;
#pragma unroll
                for (int u = 0; u < 4; u++)
                    CP_ASYNC16(sA + stsBase + u * 64 * PITCH_U * 4, pA + (size_t)u * 64 * (D / 2));
#pragma unroll
                for (int u = 0; u < 2; u++)
                    CP_ASYNC16(sB + stsBase + u * 64 * PITCH_U * 4, pB + (size_t)u * 64 * (D / 2));
                CP_COMMIT();
            }

            const uint32_t* sA = smu + OFF_TILES + (c & 1) * STAGE_U;
            const uint32_t* sB = sA + A_TILE_U;
#pragma unroll
            for (int g = 0; g < 2; g++) {
                uint32_t a0[4], a1[4], a2[4], a3[4], b0[8], b1[8];
#pragma unroll
                for (int mt = 0; mt < 4; mt++) {
                    int off = (wi * 64 + mt * 16 + tg) * PITCH_U + g * 8 + 2 * q;
                    uint2 lo = *(const uint2*)&sA[off];
                    uint2 hi = *(const uint2*)&sA[off + 8 * PITCH_U];
                    a0[mt] = lo.x; a2[mt] = lo.y;
                    a1[mt] = hi.x; a3[mt] = hi.y;
                }
#pragma unroll
                for (int nt = 0; nt < 8; nt++) {
                    uint2 bb = *(const uint2*)&sB[(wj * 64 + nt * 8 + tg) * PITCH_U + g * 8 + 2 * q];
                    b0[nt] = bb.x; b1[nt] = bb.y;
                }
#pragma unroll
                for (int mt = 0; mt < 4; mt++)
#pragma unroll
                    for (int nt = 0; nt < 8; nt++)
                        mma_bf16(acc[mt][nt], a0[mt], a1[mt], a2[mt], a3[mt],
                                 b0[nt], b1[nt]);
            }
        }

        // Epilogue.
        const float* sqi = sm + OFF_SQ + phase * 384;
        const float* sqj = sqi + 256;
#pragma unroll
        for (int mt = 0; mt < 4; mt++)
#pragma unroll
            for (int nt = 0; nt < 8; nt++)
#pragma unroll
                for (int e = 0; e < 4; e++) {
                    int lr = wi * 64 + mt * 16 + tg + ((e >> 1) << 3);
                    int lc = wj * 64 + nt * 8 + 2 * q + (e & 1);
                    float sq = sqi[lr] + sqj[lc] - 2.f * acc[mt][nt][e];
                    float dd = sq > 0.f ? sq * rsqrtf(sq) : 0.f;
                    int slot = OFF_DP + ((mt * 8 + nt) * 4 + e) * 256 + tid;
                    if (phase == 0) {
                        sm[slot] = dd;
                    } else {
                        int gi = rowI + lr, gj = rowJ + lc;
                        float w = (gj > gi) ? 2.f : 0.f;   // diag contributes 0
                        float d = sm[slot] - dd;
                        s_total += w * d * d;
                    }
                }
    }

#pragma unroll
    for (int o = 16; o; o >>= 1) s_total += __shfl_xor_sync(0xffffffffu, s_total, o);
    if (lane == 0) sm[OFF_SRED + wid] = s_total;
    __syncthreads();
    if (tid == 0) {
        double tot = 0.0;
#pragma unroll
        for (int w = 0; w < 8; w++) tot += (double)sm[OFF_SRED + w];
        atomicAdd(&g_acc[1 + f], tot);
    }
}

// ---------------------------------------------------------------------------
__global__ void final_kernel(float* __restrict__ out) {
    double label = g_acc[0] / ((double)N * (double)C);
    double feat  = (g_acc[1] + g_acc[2] + g_acc[3]) / ((double)N * (double)N);
    out[0] = (float)((1.0 - 0.8) * label + 0.8 * feat / 3.0);
}

// ---------------------------------------------------------------------------
extern "C" void kernel_launch(void* const* d_in, const int* in_sizes, int n_in,
                              void* d_out, int out_size) {
    const float* pred   = (const float*)d_in[0];
    const float* target = (const float*)d_in[1];
    const float* pf0 = (const float*)d_in[2];
    const float* pf1 = (const float*)d_in[3];
    const float* pf2 = (const float*)d_in[4];
    const float* tf0 = (const float*)d_in[5];
    const float* tf1 = (const float*)d_in[6];
    const float* tf2 = (const float*)d_in[7];
    float* out = (float*)d_out;

    static int configured = 0;
    if (!configured) {
        cudaFuncSetAttribute(pair_kernel,
                             cudaFuncAttributeMaxDynamicSharedMemorySize, SMEM_BYTES);
        configured = 1;
    }

    // prep fuses: g_acc zeroing, bf16 conversion/permute, row squared norms.
    prep_kernel<<<(6 * N * D / 16 + 255) / 256, 256>>>(pf0, pf1, pf2, tf0, tf1, tf2);
    label_kernel<<<1024, 256>>>(pred, target);

    dim3 grid(NTILES, 3);
    pair_kernel<<<grid, 256, SMEM_BYTES>>>();

    final_kernel<<<1, 1>>>(out);
}